// round 16
// baseline (speedup 1.0000x reference)
#include <cuda_runtime.h>
#include <cuda_bf16.h>
#include <math_constants.h>
#include <cstdint>

#define N_TOTAL 32768
#define DIM     256
#define KCODES  1024
#define HW      1024
#define MARGIN  2.5e-3f
#define CANDCAP 32

// ---------------- scratch ----------------
__device__ __align__(16) uint32_t g_epack[(size_t)KCODES * 128];  // bf16x2 codes, K-major
__device__ float    g_embsq[KCODES];
__device__ float    g_rowsq[N_TOTAL];
__device__ int      g_idx[N_TOTAL];
__device__ __align__(16) unsigned short g_cand[N_TOTAL][CANDCAP];
__device__ int      g_cnt[N_TOTAL];
__device__ double   g_partial[1024];

// ---------------- cp.async helpers ----------------
__device__ __forceinline__ void cp16(uint32_t saddr, const void* gaddr) {
    asm volatile("cp.async.cg.shared.global [%0], [%1], 16;" :: "r"(saddr), "l"(gaddr));
}
#define CP_COMMIT() asm volatile("cp.async.commit_group;" ::: "memory")
#define CP_WAIT(n)  asm volatile("cp.async.wait_group %0;" :: "n"(n) : "memory")

// ---------------- fused pack(e->bf16) + embsq, transpose-staged -------------
__global__ __launch_bounds__(256) void k_prep(const float* __restrict__ e) {
    __shared__ float sE[32][257];
    int tid = threadIdx.x;
    int r0 = blockIdx.x * 32;
#pragma unroll
    for (int i = 0; i < 32; i++) {
        int idx = tid + i * 256;
        int row = idx >> 8, c = idx & 255;
        sE[row][c] = e[(size_t)(r0 + row) * DIM + c];
    }
    __syncthreads();
    if (tid < 32) {
        float acc = 0.f;
#pragma unroll 8
        for (int c = 0; c < DIM; c++) {
            float v = sE[tid][c];
            acc = __fadd_rn(acc, __fmul_rn(v, v));
        }
        g_embsq[r0 + tid] = acc;
    }
#pragma unroll
    for (int i = 0; i < 16; i++) {
        int idx = tid + i * 256;
        int row = idx >> 7, cp = idx & 127;
        float f0 = sE[row][2 * cp], f1 = sE[row][2 * cp + 1];
        __nv_bfloat16 h0 = __float2bfloat16_rn(f0);
        __nv_bfloat16 h1 = __float2bfloat16_rn(f1);
        g_epack[(size_t)(r0 + row) * 128 + cp] =
            ((uint32_t)__bfloat16_as_ushort(h1) << 16) | __bfloat16_as_ushort(h0);
    }
}

// ---------------- mainloop-only: staging + rowsq + HMMA + argmin + capture --
#define SA_ST     132
#define SB_OFF    (128 * SA_ST)            // 16896
#define SB_BUF    (128 * SA_ST)
#define SBK_OFF   (SB_OFF + 2 * SB_BUF)    // 50688
#define SMINW_OFF (SBK_OFF + 1024)         // 51712
#define SBEST_OFF (SMINW_OFF + 512)        // 52224
#define SCNT_OFF  (SBEST_OFF + 128)        // 52352
#define SCAND_OFF (SCNT_OFF + 128)         // 52480 : u16 [128][32] = 2048 u32
#define SAN_OFF   (SCAND_OFF + 2048)       // 54528
#define SMEM_U32  (SAN_OFF + 128)          // 54656
#define SMEM_BYTES (SMEM_U32 * 4)          // 218624 B

__global__ __launch_bounds__(512, 1) void k_gemm(const float* __restrict__ x) {
    extern __shared__ __align__(16) uint32_t sm[];
    uint32_t* sA   = sm;
    float*    sBk  = (float*)(sm + SBK_OFF);
    float*    sMnW = (float*)(sm + SMINW_OFF);
    float*    sBest= (float*)(sm + SBEST_OFF);
    int*      sCnt = (int*)(sm + SCNT_OFF);
    unsigned short* sCand = (unsigned short*)(sm + SCAND_OFF);
    float*    sAn  = (float*)(sm + SAN_OFF);

    int tid = threadIdx.x;
    int lane = tid & 31, w = tid >> 5;
    int g = lane >> 2, tg = lane & 3;
    int wm = w & 3, wn = w >> 2;
    int n0 = blockIdx.x * 128;

    uint32_t smu;
    asm("{ .reg .u64 t; cvta.to.shared.u64 t, %1; cvt.u32.u64 %0, t; }"
        : "=r"(smu) : "l"(sm));

    // kick off panel 0 -> buf0
    {
        const uint32_t* gsrc = g_epack;
#pragma unroll
        for (int i = 0; i < 8; i++) {
            int seg = tid + i * 512, code = seg >> 5, j = seg & 31;
            cp16(smu + (uint32_t)(SB_OFF + code * SA_ST + j * 4) * 4,
                 gsrc + code * 128 + j * 4);
        }
        CP_COMMIT();
    }

    for (int i = tid; i < KCODES; i += 512) sBk[i] = g_embsq[i];
    if (tid < 128) { sCnt[tid] = 0; sBest[tid] = CUDART_INF_F; }

    // ---- A staging + rowsq; sT aliased into B buffer 1 ----
    float* sT = (float*)(sm + SB_OFF + SB_BUF);
    int b = n0 >> 10, hw0 = n0 & 1023;
    const float* xb = x + (size_t)b * DIM * HW + hw0;
    float rs = 0.f;
    for (int cc0 = 0; cc0 < 8; cc0++) {
        __syncthreads();
#pragma unroll
        for (int i = 0; i < 8; i++) {
            int idx = tid + i * 512, ci = idx >> 7, nn = idx & 127;
            sT[ci * 129 + nn] = xb[(cc0 * 32 + ci) * HW + nn];
        }
        __syncthreads();
#pragma unroll
        for (int i = 0; i < 4; i++) {
            int idx = tid + i * 512, nn = idx >> 4, cp = idx & 15;
            float f0 = sT[(2 * cp) * 129 + nn];
            float f1 = sT[(2 * cp + 1) * 129 + nn];
            __nv_bfloat16 h0 = __float2bfloat16_rn(f0);
            __nv_bfloat16 h1 = __float2bfloat16_rn(f1);
            sA[nn * SA_ST + cc0 * 16 + cp] =
                ((uint32_t)__bfloat16_as_ushort(h1) << 16) | __bfloat16_as_ushort(h0);
        }
        if (tid < 128) {   // exact sequential rowsq
#pragma unroll
            for (int c = 0; c < 32; c++) {
                float v = sT[c * 129 + tid];
                rs = __fadd_rn(rs, __fmul_rn(v, v));
            }
        }
    }
    __syncthreads();
    if (tid < 128) sAn[tid] = rs;

    // panel 1 -> buf1
    {
        const uint32_t* gsrc = g_epack + (size_t)128 * 128;
#pragma unroll
        for (int i = 0; i < 8; i++) {
            int seg = tid + i * 512, code = seg >> 5, j = seg & 31;
            cp16(smu + (uint32_t)(SB_OFF + SB_BUF + code * SA_ST + j * 4) * 4,
                 gsrc + code * 128 + j * 4);
        }
        CP_COMMIT();
    }

    for (int p = 0; p < 8; p++) {
        if (p < 7) CP_WAIT(1); else CP_WAIT(0);
        __syncthreads();
        const uint32_t* Bbuf = sm + SB_OFF + (p & 1) * SB_BUF;

        float acc[2][4][4];
#pragma unroll
        for (int mt = 0; mt < 2; mt++)
#pragma unroll
            for (int nt = 0; nt < 4; nt++)
#pragma unroll
                for (int e2 = 0; e2 < 4; e2++) acc[mt][nt][e2] = 0.f;

        const uint32_t* Ab = sA + (wm * 32 + g) * SA_ST;
        const uint32_t* Bb = Bbuf + (wn * 32 + g) * SA_ST;
#pragma unroll
        for (int ks = 0; ks < 16; ks++) {
            uint32_t a[2][4];
#pragma unroll
            for (int mt = 0; mt < 2; mt++) {
                const uint32_t* ap = Ab + mt * 16 * SA_ST + ks * 8 + tg;
                a[mt][0] = ap[0];
                a[mt][1] = ap[8 * SA_ST];
                a[mt][2] = ap[4];
                a[mt][3] = ap[8 * SA_ST + 4];
            }
#pragma unroll
            for (int nt = 0; nt < 4; nt++) {
                uint32_t b0 = Bb[nt * 8 * SA_ST + ks * 8 + tg];
                uint32_t b1 = Bb[nt * 8 * SA_ST + ks * 8 + tg + 4];
#pragma unroll
                for (int mt = 0; mt < 2; mt++) {
                    asm volatile(
                        "mma.sync.aligned.m16n8k16.row.col.f32.bf16.bf16.f32 "
                        "{%0,%1,%2,%3}, {%4,%5,%6,%7}, {%8,%9}, {%0,%1,%2,%3};"
                        : "+f"(acc[mt][nt][0]), "+f"(acc[mt][nt][1]),
                          "+f"(acc[mt][nt][2]), "+f"(acc[mt][nt][3])
                        : "r"(a[mt][0]), "r"(a[mt][1]), "r"(a[mt][2]), "r"(a[mt][3]),
                          "r"(b0), "r"(b1));
                }
            }
        }

        // ---- phase 1: per-(row,warp) min ----
        int kb = p * 128 + wn * 32 + 2 * tg;
        float bkv[4][2];
#pragma unroll
        for (int nt = 0; nt < 4; nt++) {
            bkv[nt][0] = sBk[kb + nt * 8];
            bkv[nt][1] = sBk[kb + nt * 8 + 1];
        }
        float mn[4] = {CUDART_INF_F, CUDART_INF_F, CUDART_INF_F, CUDART_INF_F};
#pragma unroll
        for (int mt = 0; mt < 2; mt++)
#pragma unroll
            for (int nt = 0; nt < 4; nt++) {
                float t0 = __fmaf_rn(-2.f, acc[mt][nt][0], bkv[nt][0]);
                float t1 = __fmaf_rn(-2.f, acc[mt][nt][1], bkv[nt][1]);
                float t2 = __fmaf_rn(-2.f, acc[mt][nt][2], bkv[nt][0]);
                float t3 = __fmaf_rn(-2.f, acc[mt][nt][3], bkv[nt][1]);
                mn[mt * 2]     = fminf(mn[mt * 2], fminf(t0, t1));
                mn[mt * 2 + 1] = fminf(mn[mt * 2 + 1], fminf(t2, t3));
            }
#pragma unroll
        for (int i = 0; i < 4; i++) {
            mn[i] = fminf(mn[i], __shfl_xor_sync(0xffffffffu, mn[i], 1));
            mn[i] = fminf(mn[i], __shfl_xor_sync(0xffffffffu, mn[i], 2));
        }
        if (tg == 0) {
#pragma unroll
            for (int mt = 0; mt < 2; mt++)
#pragma unroll
                for (int h = 0; h < 2; h++) {
                    int r = wm * 32 + mt * 16 + g + 8 * h;
                    sMnW[r * 4 + wn] = mn[mt * 2 + h];
                }
        }
        __syncthreads();

        // prefetch panel p+2
        if (p + 2 < 8) {
            const uint32_t* gsrc = g_epack + (size_t)(p + 2) * 128 * 128;
            uint32_t dst = smu + (uint32_t)(SB_OFF + (p & 1) * SB_BUF) * 4;
#pragma unroll
            for (int i = 0; i < 8; i++) {
                int seg = tid + i * 512, code = seg >> 5, j = seg & 31;
                cp16(dst + (uint32_t)(code * SA_ST + j * 4) * 4,
                     gsrc + code * 128 + j * 4);
            }
            CP_COMMIT();
        }

        // ---- phase 2: capture candidates vs global running best ----
        float thr[4];
#pragma unroll
        for (int mt = 0; mt < 2; mt++)
#pragma unroll
            for (int h = 0; h < 2; h++) {
                int r = wm * 32 + mt * 16 + g + 8 * h;
                float t4 = fminf(fminf(sMnW[r * 4 + 0], sMnW[r * 4 + 1]),
                                 fminf(sMnW[r * 4 + 2], sMnW[r * 4 + 3]));
                thr[mt * 2 + h] = fminf(sBest[r], t4);
            }
#pragma unroll
        for (int mt = 0; mt < 2; mt++)
#pragma unroll
            for (int nt = 0; nt < 4; nt++)
#pragma unroll
                for (int e2 = 0; e2 < 4; e2++) {
                    float t = __fmaf_rn(-2.f, acc[mt][nt][e2], bkv[nt][e2 & 1]);
                    int h = e2 >> 1;
                    if (t <= thr[mt * 2 + h] + MARGIN) {
                        int r = wm * 32 + mt * 16 + g + 8 * h;
                        int k = kb + nt * 8 + (e2 & 1);
                        int pos = atomicAdd(&sCnt[r], 1);
                        if (pos < CANDCAP) sCand[r * CANDCAP + pos] = (unsigned short)k;
                    }
                }
        __syncthreads();
        if (wn == 0 && tg == 0) {
#pragma unroll
            for (int mt = 0; mt < 2; mt++)
#pragma unroll
                for (int h = 0; h < 2; h++) {
                    int r = wm * 32 + mt * 16 + g + 8 * h;
                    sBest[r] = thr[mt * 2 + h];
                }
        }
    }
    __syncthreads();

    // ---- write capture state to global (rescore runs as its own kernel) ----
    if (tid < 128) {
        g_cnt[n0 + tid] = sCnt[tid];
        g_rowsq[n0 + tid] = sAn[tid];
    }
    uint32_t* gc = (uint32_t*)&g_cand[n0][0];     // 128*32 u16 = 2048 u32, contiguous
#pragma unroll 1
    for (int i = tid; i < 2048; i += 512) gc[i] = ((uint32_t*)sCand)[i];
}

// ---------------- exact rescore (R4 chain; grouped ILP; coalesced x) --------
__global__ __launch_bounds__(128) void k_rescore(const float* __restrict__ x,
                                                 const float* __restrict__ e) {
    int n = blockIdx.x * 128 + threadIdx.x;
    int cnt = g_cnt[n];
    if (cnt == 1) { g_idx[n] = g_cand[n][0]; return; }
    int b = n >> 10, hw = n & 1023;
    const float* xp = x + (size_t)b * DIM * HW + hw;
    float an = g_rowsq[n];
    bool full = cnt > CANDCAP;
    int m = full ? KCODES : cnt;
    float bestS = CUDART_INF_F;
    int best = 0x7fffffff;
    for (int base = 0; base < m; base += 4) {
        int kk[4];
#pragma unroll
        for (int i = 0; i < 4; i++) {
            int s = base + i;
            int sc = (s < m) ? s : m - 1;
            kk[i] = full ? sc : (int)g_cand[n][sc];
        }
        const float* e0 = e + (size_t)kk[0] * DIM;
        const float* e1 = e + (size_t)kk[1] * DIM;
        const float* e2 = e + (size_t)kk[2] * DIM;
        const float* e3 = e + (size_t)kk[3] * DIM;
        float a0 = 0.f, a1 = 0.f, a2 = 0.f, a3 = 0.f;
#pragma unroll 4
        for (int cc = 0; cc < DIM; cc++) {
            float xv = xp[cc * HW];
            a0 = __fmaf_rn(xv, e0[cc], a0);
            a1 = __fmaf_rn(xv, e1[cc], a1);
            a2 = __fmaf_rn(xv, e2[cc], a2);
            a3 = __fmaf_rn(xv, e3[cc], a3);
        }
        float av[4] = {a0, a1, a2, a3};
#pragma unroll
        for (int i = 0; i < 4; i++) {
            if (base + i < m) {
                float s = __fsub_rn(__fadd_rn(an, g_embsq[kk[i]]),
                                    __fmul_rn(2.0f, av[i]));
                if (s < bestS || (s == bestS && kk[i] < best)) { bestS = s; best = kk[i]; }
            }
        }
    }
    g_idx[n] = best;
}

// ---------------- fused outputs: quantized_st + one-hot encodings + loss ----
__global__ __launch_bounds__(256) void k_out(const float* __restrict__ x,
                                             const float* __restrict__ emb,
                                             float* __restrict__ out) {
    int rowl = threadIdx.x & 31, sub = threadIdx.x >> 5;
    int n = blockIdx.x * 32 + rowl;
    int b = n >> 10, hw = n & 1023;
    const float* xp = x + (size_t)b * DIM * HW + hw;
    float* qp = out + 1 + (size_t)b * DIM * HW + hw;
    int idx = g_idx[n];
    const float* ep = emb + (size_t)idx * DIM;
    double ssum = 0.0;
    int c0 = sub * 32;
#pragma unroll 4
    for (int i = 0; i < 32; i++) {
        int c = c0 + i;
        float in = xp[c * HW];
        float q  = ep[c];
        float d  = __fsub_rn(q, in);          // fl(q - in)
        float st = __fadd_rn(in, d);          // fl(in + d)
        qp[c * HW] = st;
        ssum += (double)__fmul_rn(d, d);
    }

    // one-hot encodings, warp-per-row coalesced
    int lane = rowl;
#pragma unroll
    for (int rr = 0; rr < 4; rr++) {
        int n2 = blockIdx.x * 32 + sub * 4 + rr;
        int idx2 = g_idx[n2];
        float* seg = out + 1 + (size_t)N_TOTAL * DIM + (size_t)n2 * KCODES;
        if (lane < 3) seg[lane] = 0.f;
        if (lane == 3) seg[1023] = 0.f;
        uint4* v4 = (uint4*)(seg + 3);
#pragma unroll
        for (int it = 0; it < 8; it++) {
            int i = it * 32 + lane;
            if (i < 255) v4[i] = make_uint4(0, 0, 0, 0);
        }
        __syncwarp();
        if (lane == 0) seg[idx2] = 1.0f;
    }

    __shared__ double sred[256];
    sred[threadIdx.x] = ssum;
    __syncthreads();
    for (int s = 128; s > 0; s >>= 1) {
        if (threadIdx.x < s) sred[threadIdx.x] += sred[threadIdx.x + s];
        __syncthreads();
    }
    if (threadIdx.x == 0) g_partial[blockIdx.x] = sred[0];
}

__global__ void k_loss(float* __restrict__ out) {
    __shared__ double sred[256];
    double a = 0.0;
#pragma unroll
    for (int i = 0; i < 4; i++) a += g_partial[threadIdx.x * 4 + i];
    sred[threadIdx.x] = a;
    __syncthreads();
    for (int s = 128; s > 0; s >>= 1) {
        if (threadIdx.x < s) sred[threadIdx.x] += sred[threadIdx.x + s];
        __syncthreads();
    }
    if (threadIdx.x == 0) {
        double m = sred[0] / (double)((long long)N_TOTAL * DIM);
        out[0] = (float)(m + 0.25 * m);
    }
}

extern "C" void kernel_launch(void* const* d_in, const int* in_sizes, int n_in,
                              void* d_out, int out_size) {
    const float* x = (const float*)d_in[0];
    const float* e = (const float*)d_in[1];
    if (n_in >= 2 && in_sizes[0] == KCODES * DIM && in_sizes[1] == N_TOTAL * DIM) {
        x = (const float*)d_in[1];
        e = (const float*)d_in[0];
    }
    float* out = (float*)d_out;

    cudaFuncSetAttribute(k_gemm, cudaFuncAttributeMaxDynamicSharedMemorySize, SMEM_BYTES);

    k_prep<<<32, 256>>>(e);
    k_gemm<<<N_TOTAL / 128, 512, SMEM_BYTES>>>(x);
    k_rescore<<<N_TOTAL / 128, 128>>>(x, e);
    k_out<<<N_TOTAL / 32, 256>>>(x, e, out);
    k_loss<<<1, 256>>>(out);
}

// round 17
// speedup vs baseline: 1.1101x; 1.1101x over previous
#include <cuda_runtime.h>
#include <cuda_bf16.h>
#include <math_constants.h>
#include <cstdint>

#define N_TOTAL 32768
#define DIM     256
#define KCODES  1024
#define HW      1024
#define MARGIN  2.5e-3f
#define CANDCAP 96

// ---------------- scratch ----------------
__device__ __align__(16) uint32_t g_epack[(size_t)KCODES * 128];  // bf16x2 codes, K-major
__device__ float    g_embsq[KCODES];
__device__ float    g_rowsq[N_TOTAL];
__device__ int      g_idx[N_TOTAL];
// transposed [pos][n] so rescore reads coalesce across lanes (consecutive n)
__device__ unsigned short g_cand[(size_t)CANDCAP * N_TOTAL];
__device__ float          g_cscore[(size_t)CANDCAP * N_TOTAL];
__device__ int      g_cnt[N_TOTAL];
__device__ double   g_partial[1024];

// ---------------- cp.async helpers ----------------
__device__ __forceinline__ void cp16(uint32_t saddr, const void* gaddr) {
    asm volatile("cp.async.cg.shared.global [%0], [%1], 16;" :: "r"(saddr), "l"(gaddr));
}
#define CP_COMMIT() asm volatile("cp.async.commit_group;" ::: "memory")
#define CP_WAIT(n)  asm volatile("cp.async.wait_group %0;" :: "n"(n) : "memory")

// ---------------- fused pack(e->bf16) + embsq, transpose-staged -------------
__global__ __launch_bounds__(256) void k_prep(const float* __restrict__ e) {
    __shared__ float sE[32][257];
    int tid = threadIdx.x;
    int r0 = blockIdx.x * 32;
#pragma unroll
    for (int i = 0; i < 32; i++) {
        int idx = tid + i * 256;
        int row = idx >> 8, c = idx & 255;
        sE[row][c] = e[(size_t)(r0 + row) * DIM + c];
    }
    __syncthreads();
    if (tid < 32) {
        float acc = 0.f;
#pragma unroll 8
        for (int c = 0; c < DIM; c++) {
            float v = sE[tid][c];
            acc = __fadd_rn(acc, __fmul_rn(v, v));
        }
        g_embsq[r0 + tid] = acc;
    }
#pragma unroll
    for (int i = 0; i < 16; i++) {
        int idx = tid + i * 256;
        int row = idx >> 7, cp = idx & 127;
        float f0 = sE[row][2 * cp], f1 = sE[row][2 * cp + 1];
        __nv_bfloat16 h0 = __float2bfloat16_rn(f0);
        __nv_bfloat16 h1 = __float2bfloat16_rn(f1);
        g_epack[(size_t)(r0 + row) * 128 + cp] =
            ((uint32_t)__bfloat16_as_ushort(h1) << 16) | __bfloat16_as_ushort(h0);
    }
}

// ---------------- mainloop: staging + rowsq + HMMA + argmin + capture -------
#define SA_ST     132
#define SB_OFF    (128 * SA_ST)            // 16896
#define SB_BUF    (128 * SA_ST)
#define SBK_OFF   (SB_OFF + 2 * SB_BUF)    // 50688
#define SMINW_OFF (SBK_OFF + 1024)         // 51712
#define SBEST_OFF (SMINW_OFF + 512)        // 52224
#define SCNT_OFF  (SBEST_OFF + 128)        // 52352
#define SAN_OFF   (SCNT_OFF + 128)         // 52480
#define SMEM_U32  (SAN_OFF + 128)          // 52608
#define SMEM_BYTES (SMEM_U32 * 4)          // 210432 B

__global__ __launch_bounds__(512, 1) void k_gemm(const float* __restrict__ x) {
    extern __shared__ __align__(16) uint32_t sm[];
    uint32_t* sA   = sm;
    float*    sBk  = (float*)(sm + SBK_OFF);
    float*    sMnW = (float*)(sm + SMINW_OFF);
    float*    sBest= (float*)(sm + SBEST_OFF);
    int*      sCnt = (int*)(sm + SCNT_OFF);
    float*    sAn  = (float*)(sm + SAN_OFF);

    int tid = threadIdx.x;
    int lane = tid & 31, w = tid >> 5;
    int g = lane >> 2, tg = lane & 3;
    int wm = w & 3, wn = w >> 2;
    int n0 = blockIdx.x * 128;

    uint32_t smu;
    asm("{ .reg .u64 t; cvta.to.shared.u64 t, %1; cvt.u32.u64 %0, t; }"
        : "=r"(smu) : "l"(sm));

    // kick off panel 0 -> buf0
    {
        const uint32_t* gsrc = g_epack;
#pragma unroll
        for (int i = 0; i < 8; i++) {
            int seg = tid + i * 512, code = seg >> 5, j = seg & 31;
            cp16(smu + (uint32_t)(SB_OFF + code * SA_ST + j * 4) * 4,
                 gsrc + code * 128 + j * 4);
        }
        CP_COMMIT();
    }

    for (int i = tid; i < KCODES; i += 512) sBk[i] = g_embsq[i];
    if (tid < 128) { sCnt[tid] = 0; sBest[tid] = CUDART_INF_F; }

    // ---- A staging + rowsq; sT aliased into B buffer 1 ----
    float* sT = (float*)(sm + SB_OFF + SB_BUF);
    int b = n0 >> 10, hw0 = n0 & 1023;
    const float* xb = x + (size_t)b * DIM * HW + hw0;
    float rs = 0.f;
    for (int cc0 = 0; cc0 < 8; cc0++) {
        __syncthreads();
#pragma unroll
        for (int i = 0; i < 8; i++) {
            int idx = tid + i * 512, ci = idx >> 7, nn = idx & 127;
            sT[ci * 129 + nn] = xb[(cc0 * 32 + ci) * HW + nn];
        }
        __syncthreads();
#pragma unroll
        for (int i = 0; i < 4; i++) {
            int idx = tid + i * 512, nn = idx >> 4, cp = idx & 15;
            float f0 = sT[(2 * cp) * 129 + nn];
            float f1 = sT[(2 * cp + 1) * 129 + nn];
            __nv_bfloat16 h0 = __float2bfloat16_rn(f0);
            __nv_bfloat16 h1 = __float2bfloat16_rn(f1);
            sA[nn * SA_ST + cc0 * 16 + cp] =
                ((uint32_t)__bfloat16_as_ushort(h1) << 16) | __bfloat16_as_ushort(h0);
        }
        if (tid < 128) {   // exact sequential rowsq
#pragma unroll
            for (int c = 0; c < 32; c++) {
                float v = sT[c * 129 + tid];
                rs = __fadd_rn(rs, __fmul_rn(v, v));
            }
        }
    }
    __syncthreads();
    if (tid < 128) sAn[tid] = rs;

    // panel 1 -> buf1
    {
        const uint32_t* gsrc = g_epack + (size_t)128 * 128;
#pragma unroll
        for (int i = 0; i < 8; i++) {
            int seg = tid + i * 512, code = seg >> 5, j = seg & 31;
            cp16(smu + (uint32_t)(SB_OFF + SB_BUF + code * SA_ST + j * 4) * 4,
                 gsrc + code * 128 + j * 4);
        }
        CP_COMMIT();
    }

    for (int p = 0; p < 8; p++) {
        if (p < 7) CP_WAIT(1); else CP_WAIT(0);
        __syncthreads();
        const uint32_t* Bbuf = sm + SB_OFF + (p & 1) * SB_BUF;

        float acc[2][4][4];
#pragma unroll
        for (int mt = 0; mt < 2; mt++)
#pragma unroll
            for (int nt = 0; nt < 4; nt++)
#pragma unroll
                for (int e2 = 0; e2 < 4; e2++) acc[mt][nt][e2] = 0.f;

        const uint32_t* Ab = sA + (wm * 32 + g) * SA_ST;
        const uint32_t* Bb = Bbuf + (wn * 32 + g) * SA_ST;
#pragma unroll
        for (int ks = 0; ks < 16; ks++) {
            uint32_t a[2][4];
#pragma unroll
            for (int mt = 0; mt < 2; mt++) {
                const uint32_t* ap = Ab + mt * 16 * SA_ST + ks * 8 + tg;
                a[mt][0] = ap[0];
                a[mt][1] = ap[8 * SA_ST];
                a[mt][2] = ap[4];
                a[mt][3] = ap[8 * SA_ST + 4];
            }
#pragma unroll
            for (int nt = 0; nt < 4; nt++) {
                uint32_t b0 = Bb[nt * 8 * SA_ST + ks * 8 + tg];
                uint32_t b1 = Bb[nt * 8 * SA_ST + ks * 8 + tg + 4];
#pragma unroll
                for (int mt = 0; mt < 2; mt++) {
                    asm volatile(
                        "mma.sync.aligned.m16n8k16.row.col.f32.bf16.bf16.f32 "
                        "{%0,%1,%2,%3}, {%4,%5,%6,%7}, {%8,%9}, {%0,%1,%2,%3};"
                        : "+f"(acc[mt][nt][0]), "+f"(acc[mt][nt][1]),
                          "+f"(acc[mt][nt][2]), "+f"(acc[mt][nt][3])
                        : "r"(a[mt][0]), "r"(a[mt][1]), "r"(a[mt][2]), "r"(a[mt][3]),
                          "r"(b0), "r"(b1));
                }
            }
        }

        // ---- phase 1: per-(row,warp) min ----
        int kb = p * 128 + wn * 32 + 2 * tg;
        float bkv[4][2];
#pragma unroll
        for (int nt = 0; nt < 4; nt++) {
            bkv[nt][0] = sBk[kb + nt * 8];
            bkv[nt][1] = sBk[kb + nt * 8 + 1];
        }
        float mn[4] = {CUDART_INF_F, CUDART_INF_F, CUDART_INF_F, CUDART_INF_F};
#pragma unroll
        for (int mt = 0; mt < 2; mt++)
#pragma unroll
            for (int nt = 0; nt < 4; nt++) {
                float t0 = __fmaf_rn(-2.f, acc[mt][nt][0], bkv[nt][0]);
                float t1 = __fmaf_rn(-2.f, acc[mt][nt][1], bkv[nt][1]);
                float t2 = __fmaf_rn(-2.f, acc[mt][nt][2], bkv[nt][0]);
                float t3 = __fmaf_rn(-2.f, acc[mt][nt][3], bkv[nt][1]);
                mn[mt * 2]     = fminf(mn[mt * 2], fminf(t0, t1));
                mn[mt * 2 + 1] = fminf(mn[mt * 2 + 1], fminf(t2, t3));
            }
#pragma unroll
        for (int i = 0; i < 4; i++) {
            mn[i] = fminf(mn[i], __shfl_xor_sync(0xffffffffu, mn[i], 1));
            mn[i] = fminf(mn[i], __shfl_xor_sync(0xffffffffu, mn[i], 2));
        }
        if (tg == 0) {
#pragma unroll
            for (int mt = 0; mt < 2; mt++)
#pragma unroll
                for (int h = 0; h < 2; h++) {
                    int r = wm * 32 + mt * 16 + g + 8 * h;
                    sMnW[r * 4 + wn] = mn[mt * 2 + h];
                }
        }
        __syncthreads();

        // prefetch panel p+2
        if (p + 2 < 8) {
            const uint32_t* gsrc = g_epack + (size_t)(p + 2) * 128 * 128;
            uint32_t dst = smu + (uint32_t)(SB_OFF + (p & 1) * SB_BUF) * 4;
#pragma unroll
            for (int i = 0; i < 8; i++) {
                int seg = tid + i * 512, code = seg >> 5, j = seg & 31;
                cp16(dst + (uint32_t)(code * SA_ST + j * 4) * 4,
                     gsrc + code * 128 + j * 4);
            }
            CP_COMMIT();
        }

        // ---- phase 2: capture (idx, approx score) vs running best ----
        float thr[4];
#pragma unroll
        for (int mt = 0; mt < 2; mt++)
#pragma unroll
            for (int h = 0; h < 2; h++) {
                int r = wm * 32 + mt * 16 + g + 8 * h;
                float t4 = fminf(fminf(sMnW[r * 4 + 0], sMnW[r * 4 + 1]),
                                 fminf(sMnW[r * 4 + 2], sMnW[r * 4 + 3]));
                thr[mt * 2 + h] = fminf(sBest[r], t4);
            }
#pragma unroll
        for (int mt = 0; mt < 2; mt++)
#pragma unroll
            for (int nt = 0; nt < 4; nt++)
#pragma unroll
                for (int e2 = 0; e2 < 4; e2++) {
                    float t = __fmaf_rn(-2.f, acc[mt][nt][e2], bkv[nt][e2 & 1]);
                    int h = e2 >> 1;
                    if (t <= thr[mt * 2 + h] + MARGIN) {
                        int r = wm * 32 + mt * 16 + g + 8 * h;
                        int k = kb + nt * 8 + (e2 & 1);
                        int pos = atomicAdd(&sCnt[r], 1);
                        if (pos < CANDCAP) {
                            size_t off = (size_t)pos * N_TOTAL + n0 + r;
                            g_cand[off]   = (unsigned short)k;
                            g_cscore[off] = t;
                        }
                    }
                }
        __syncthreads();
        if (wn == 0 && tg == 0) {
#pragma unroll
            for (int mt = 0; mt < 2; mt++)
#pragma unroll
                for (int h = 0; h < 2; h++) {
                    int r = wm * 32 + mt * 16 + g + 8 * h;
                    sBest[r] = thr[mt * 2 + h];
                }
        }
    }
    __syncthreads();

    if (tid < 128) {
        g_cnt[n0 + tid] = sCnt[tid];
        g_rowsq[n0 + tid] = sAn[tid];
    }
}

// ---------------- exact rescore: score-filter then R4-exact dots ------------
__global__ __launch_bounds__(128) void k_rescore(const float* __restrict__ x,
                                                 const float* __restrict__ e) {
    int n = blockIdx.x * 128 + threadIdx.x;
    int cnt = g_cnt[n];
    if (cnt == 1) { g_idx[n] = g_cand[n]; return; }   // pos 0, coalesced
    int b = n >> 10, hw = n & 1023;
    const float* xp = x + (size_t)b * DIM * HW + hw;
    float an = g_rowsq[n];
    float bestS = CUDART_INF_F;
    int best = 0x7fffffff;

    unsigned short surv[CANDCAP];
    int ns = 0;
    bool full = cnt > CANDCAP;
    if (!full) {
        // pass 1: global approx min over captured scores (guaranteed captured)
        float mt = CUDART_INF_F;
        for (int i = 0; i < cnt; i++)
            mt = fminf(mt, g_cscore[(size_t)i * N_TOTAL + n]);
        float thrF = mt + MARGIN;
        // pass 2: survivors only
        for (int i = 0; i < cnt; i++) {
            size_t off = (size_t)i * N_TOTAL + n;
            if (g_cscore[off] <= thrF) surv[ns++] = g_cand[off];
        }
    }
    int m = full ? KCODES : ns;

    for (int base = 0; base < m; base += 4) {
        int kk[4];
#pragma unroll
        for (int i = 0; i < 4; i++) {
            int s = base + i;
            int sc = (s < m) ? s : m - 1;
            kk[i] = full ? sc : (int)surv[sc];
        }
        const float* e0 = e + (size_t)kk[0] * DIM;
        const float* e1 = e + (size_t)kk[1] * DIM;
        const float* e2 = e + (size_t)kk[2] * DIM;
        const float* e3 = e + (size_t)kk[3] * DIM;
        float a0 = 0.f, a1 = 0.f, a2 = 0.f, a3 = 0.f;
#pragma unroll 4
        for (int cc = 0; cc < DIM; cc++) {
            float xv = xp[cc * HW];
            a0 = __fmaf_rn(xv, e0[cc], a0);
            a1 = __fmaf_rn(xv, e1[cc], a1);
            a2 = __fmaf_rn(xv, e2[cc], a2);
            a3 = __fmaf_rn(xv, e3[cc], a3);
        }
        float av[4] = {a0, a1, a2, a3};
#pragma unroll
        for (int i = 0; i < 4; i++) {
            if (base + i < m) {
                float s = __fsub_rn(__fadd_rn(an, g_embsq[kk[i]]),
                                    __fmul_rn(2.0f, av[i]));
                if (s < bestS || (s == bestS && kk[i] < best)) { bestS = s; best = kk[i]; }
            }
        }
    }
    g_idx[n] = best;
}

// ---------------- fused outputs: quantized_st + one-hot encodings + loss ----
__global__ __launch_bounds__(256) void k_out(const float* __restrict__ x,
                                             const float* __restrict__ emb,
                                             float* __restrict__ out) {
    int rowl = threadIdx.x & 31, sub = threadIdx.x >> 5;
    int n = blockIdx.x * 32 + rowl;
    int b = n >> 10, hw = n & 1023;
    const float* xp = x + (size_t)b * DIM * HW + hw;
    float* qp = out + 1 + (size_t)b * DIM * HW + hw;
    int idx = g_idx[n];
    const float* ep = emb + (size_t)idx * DIM;
    double ssum = 0.0;
    int c0 = sub * 32;
#pragma unroll 4
    for (int i = 0; i < 32; i++) {
        int c = c0 + i;
        float in = xp[c * HW];
        float q  = ep[c];
        float d  = __fsub_rn(q, in);          // fl(q - in)
        float st = __fadd_rn(in, d);          // fl(in + d)
        qp[c * HW] = st;
        ssum += (double)__fmul_rn(d, d);
    }

    // one-hot encodings, warp-per-row coalesced
    int lane = rowl;
#pragma unroll
    for (int rr = 0; rr < 4; rr++) {
        int n2 = blockIdx.x * 32 + sub * 4 + rr;
        int idx2 = g_idx[n2];
        float* seg = out + 1 + (size_t)N_TOTAL * DIM + (size_t)n2 * KCODES;
        if (lane < 3) seg[lane] = 0.f;
        if (lane == 3) seg[1023] = 0.f;
        uint4* v4 = (uint4*)(seg + 3);
#pragma unroll
        for (int it = 0; it < 8; it++) {
            int i = it * 32 + lane;
            if (i < 255) v4[i] = make_uint4(0, 0, 0, 0);
        }
        __syncwarp();
        if (lane == 0) seg[idx2] = 1.0f;
    }

    __shared__ double sred[256];
    sred[threadIdx.x] = ssum;
    __syncthreads();
    for (int s = 128; s > 0; s >>= 1) {
        if (threadIdx.x < s) sred[threadIdx.x] += sred[threadIdx.x + s];
        __syncthreads();
    }
    if (threadIdx.x == 0) g_partial[blockIdx.x] = sred[0];
}

__global__ void k_loss(float* __restrict__ out) {
    __shared__ double sred[256];
    double a = 0.0;
#pragma unroll
    for (int i = 0; i < 4; i++) a += g_partial[threadIdx.x * 4 + i];
    sred[threadIdx.x] = a;
    __syncthreads();
    for (int s = 128; s > 0; s >>= 1) {
        if (threadIdx.x < s) sred[threadIdx.x] += sred[threadIdx.x + s];
        __syncthreads();
    }
    if (threadIdx.x == 0) {
        double m = sred[0] / (double)((long long)N_TOTAL * DIM);
        out[0] = (float)(m + 0.25 * m);
    }
}

extern "C" void kernel_launch(void* const* d_in, const int* in_sizes, int n_in,
                              void* d_out, int out_size) {
    const float* x = (const float*)d_in[0];
    const float* e = (const float*)d_in[1];
    if (n_in >= 2 && in_sizes[0] == KCODES * DIM && in_sizes[1] == N_TOTAL * DIM) {
        x = (const float*)d_in[1];
        e = (const float*)d_in[0];
    }
    float* out = (float*)d_out;

    cudaFuncSetAttribute(k_gemm, cudaFuncAttributeMaxDynamicSharedMemorySize, SMEM_BYTES);

    k_prep<<<32, 256>>>(e);
    k_gemm<<<N_TOTAL / 128, 512, SMEM_BYTES>>>(x);
    k_rescore<<<N_TOTAL / 128, 128>>>(x, e);
    k_out<<<N_TOTAL / 32, 256>>>(x, e, out);
    k_loss<<<1, 256>>>(out);
}